// round 11
// baseline (speedup 1.0000x reference)
#include <cuda_runtime.h>

#define FULLMASK 0xffffffffu

typedef unsigned long long u64;

constexpr int BATCH  = 65536;
constexpr int HOFF   = BATCH * 5;      // h output offset (q first, then h)

// ===================== kernel A (attention, stages 0-5) =====================
constexpr int WARPS_A   = 16;
constexpr int EPW_A     = 4;
constexpr int THREADS_A = WARPS_A * 32;    // 512

constexpr int A_WINT  = 0;       // 3 * 64 rows * 12 = 2304
constexpr int A_BIN   = 2304;    // 192
constexpr int A_WA    = 2496;    // 128
constexpr int A_WO1T  = 2624;    // 384
constexpr int A_BO1   = 3008;    // 32
constexpr int A_WO2T  = 3040;    // 576
constexpr int A_BO2   = 3616;    // 16
constexpr int A_WO3   = 3632;    // 16
constexpr int A_BO3   = 3648;    // 4
constexpr int A_SCR   = 3652;

constexpr int ASC_OBS = 0;    // 88 (obs 85 + pad)
constexpr int ASC_U1  = 88;   // 160: HP1 5x32
constexpr int ASC_U2  = 248;  // 84: WH 20 | ATT 5x12 @+24 | HP2 80
constexpr int ASC_WH  = ASC_U2;
constexpr int ASC_ATT = ASC_U2 + 24;
constexpr int ASC_HP2 = ASC_U2;
constexpr int A_STRIDE = 336;

constexpr int SMEM_A = (A_SCR + WARPS_A * EPW_A * A_STRIDE) * 4;   // 100624 B

// ===================== kernel B (fc1 + GRU + q, stages 6-7) =================
constexpr int WARPS_B   = 16;
constexpr int EPW_B     = 8;
constexpr int THREADS_B = WARPS_B * 32;    // 512

constexpr int B_WFC1T = 0;       // 64 rows * 92 = 5888
constexpr int B_BFC1  = 5888;    // 64
constexpr int B_WFC2  = 5952;    // 320
constexpr int B_BFC2  = 6272;    // 8
constexpr int B_WIHT  = 6280;    // 192 rows * 68 = 13056
constexpr int B_BIH   = 19336;   // 192
constexpr int B_WHHT  = 19528;   // 13056
constexpr int B_BHH   = 32584;   // 192
constexpr int B_SCR   = 32776;

// X aliases OBS[0..63] (OBS dead after stage-6 reads, which precede X stores)
constexpr int BSC_OBS = 0;    // 92 (obs 85 + obs_out 5 + pads 90,91=0)
constexpr int BSC_X   = 0;    // 64, overlays OBS
constexpr int BSC_HIN = 92;   // 64
constexpr int B_STRIDE = 160;

constexpr int SMEM_B = (B_SCR + WARPS_B * EPW_B * B_STRIDE) * 4;   // 213024 B

__device__ float g_obs_out[BATCH * 5];

__device__ __forceinline__ float leakyf(float x)    { return fmaxf(x, 0.01f * x); }
__device__ __forceinline__ float sigmoidf_(float x) { return 1.0f / (1.0f + __expf(-x)); }
__device__ __forceinline__ float tanhf_(float x)    { float t = __expf(2.0f * x); return 1.0f - __fdividef(2.0f, t + 1.0f); }

__device__ __forceinline__ void dfma2(u64& acc, u64 v, u64 w) {
    asm("fma.rn.f32x2 %0, %1, %2, %0;" : "+l"(acc) : "l"(v), "l"(w));
}
__device__ __forceinline__ float f2sum(u64 a) {
    float lo, hi;
    asm("mov.b64 {%0, %1}, %2;" : "=f"(lo), "=f"(hi) : "l"(a));
    return lo + hi;
}
__device__ __forceinline__ ulonglong2 lp4(const float* p) {
    return *reinterpret_cast<const ulonglong2*>(p);
}

// ============================================================================
// Kernel A: stages 0-5 -> g_obs_out   (16 warps x EPW 4 — R8 proven config)
// ============================================================================
__global__ __launch_bounds__(THREADS_A, 1)
void atom_rnn_attn(
    const float* __restrict__ obs,
    const float* __restrict__ w_in0,  const float* __restrict__ b_in0,
    const float* __restrict__ w_in1,  const float* __restrict__ b_in1,
    const float* __restrict__ w_in2,  const float* __restrict__ b_in2,
    const float* __restrict__ W,      const float* __restrict__ a,
    const float* __restrict__ w_o1,   const float* __restrict__ b_o1,
    const float* __restrict__ w_o2,   const float* __restrict__ b_o2,
    const float* __restrict__ w_o3,   const float* __restrict__ b_o3)
{
    extern __shared__ float sm[];
    const int tid = threadIdx.x;
    const int wid = tid >> 5;
    const int l   = tid & 31;

    // ---- weight staging ----
    for (int i = tid; i < 512; i += THREADS_A) {
        int f = i >> 6, r = i & 63;
        sm[A_WINT +        r * 12 + f] = w_in0[i];
        sm[A_WINT +  768 + r * 12 + f] = w_in1[i];
        sm[A_WINT + 1536 + r * 12 + f] = w_in2[i];
    }
    for (int i = tid; i < 320; i += THREADS_A) {
        int c = i >> 5, o = i & 31;
        sm[A_WO1T + o * 12 + c] = w_o1[i];
    }
    if (tid < 64) sm[A_WO1T + (tid >> 1) * 12 + 10 + (tid & 1)] = 0.f;
    for (int i = tid; i < 512; i += THREADS_A) {
        int c = i >> 4, o = i & 15;
        sm[A_WO2T + o * 36 + c] = w_o2[i];
    }
    if (tid < 64) {
        sm[A_BIN + tid]       = b_in0[tid];
        sm[A_BIN + 64 + tid]  = b_in1[tid];
        sm[A_BIN + 128 + tid] = b_in2[tid];
        float a0 = 0.f, a1 = 0.f;                  // fold W @ a
        for (int i = 0; i < 64; i++) {
            float w = W[i * 64 + tid];
            a0 += w * a[i];
            a1 += w * a[64 + i];
        }
        sm[A_WA + tid]      = a0;
        sm[A_WA + 64 + tid] = a1;
    }
    if (tid < 32) sm[A_BO1 + tid] = b_o1[tid];
    if (tid < 16) { sm[A_BO2 + tid] = b_o2[tid]; sm[A_WO3 + tid] = w_o3[tid]; }
    if (tid == 0) sm[A_BO3] = b_o3[0];
    __syncthreads();

    float* scr = sm + A_SCR + (wid * EPW_A) * A_STRIDE;
    const int stride = gridDim.x * WARPS_A * EPW_A;

    const float wa0l = sm[A_WA + l],      wa0h = sm[A_WA + 32 + l];
    const float wa1l = sm[A_WA + 64 + l], wa1h = sm[A_WA + 96 + l];

    for (int e0 = (blockIdx.x * WARPS_A + wid) * EPW_A; e0 < BATCH; e0 += stride) {

        // ---- stage 0: load obs ----
        #pragma unroll
        for (int e = 0; e < EPW_A; e++) {
            const float* op = obs + (size_t)(e0 + e) * 85;
            float* s = scr + e * A_STRIDE;
            #pragma unroll
            for (int i = 0; i < 3; i++) {
                int idx = l + i * 32;
                if (idx < 85) s[ASC_OBS + idx] = op[idx];
            }
        }
        __syncwarp();

        // ---- stage 1: token nets (hoisted weights, packed) -> WH[0..19] ----
        {
            ulonglong2 wlA, wlB, whA, whB; float blo, bhi;
            {
                const float* wb = sm + A_WINT;   // net 0
                wlA = lp4(wb + l * 12);        wlB = lp4(wb + l * 12 + 4);
                whA = lp4(wb + (l + 32) * 12); whB = lp4(wb + (l + 32) * 12 + 4);
                blo = sm[A_BIN + l]; bhi = sm[A_BIN + 32 + l];
            }
            #pragma unroll
            for (int tp = 0; tp < 5; tp++) {
                float P1[2][EPW_A], P2[2][EPW_A];
                #pragma unroll
                for (int half = 0; half < 2; half++) {
                    const int t = 2 * tp + half;
                    if (t == 5) {
                        const float* wb = sm + A_WINT + 768;   // net 1
                        wlA = lp4(wb + l * 12);        wlB = lp4(wb + l * 12 + 4);
                        whA = lp4(wb + (l + 32) * 12); whB = lp4(wb + (l + 32) * 12 + 4);
                        blo = sm[A_BIN + 64 + l]; bhi = sm[A_BIN + 96 + l];
                    }
                    if (t == 9) {
                        const float* wb = sm + A_WINT + 1536;  // net 2
                        wlA = lp4(wb + l * 12);        wlB = lp4(wb + l * 12 + 4);
                        whA = lp4(wb + (l + 32) * 12); whB = lp4(wb + (l + 32) * 12 + 4);
                        blo = sm[A_BIN + 128 + l]; bhi = sm[A_BIN + 160 + l];
                    }
                    #pragma unroll
                    for (int e = 0; e < EPW_A; e++) {
                        const float* s = scr + e * A_STRIDE;
                        ulonglong2 v0 = lp4(s + ASC_OBS + t * 8 + 4);
                        ulonglong2 v1 = (t == 9) ? lp4(s + ASC_OBS) : lp4(s + ASC_OBS + t * 8 + 8);
                        u64 accl = 0, acch = 0;
                        dfma2(accl, v0.x, wlA.x); dfma2(accl, v0.y, wlA.y);
                        dfma2(accl, v1.x, wlB.x); dfma2(accl, v1.y, wlB.y);
                        dfma2(acch, v0.x, whA.x); dfma2(acch, v0.y, whA.y);
                        dfma2(acch, v1.x, whB.x); dfma2(acch, v1.y, whB.y);
                        float hl = leakyf(blo + f2sum(accl));
                        float hh = leakyf(bhi + f2sum(acch));
                        P1[half][e] = hl * wa0l + hh * wa0h;
                        P2[half][e] = hl * wa1l + hh * wa1h;
                    }
                }
                const int t = 2 * tp;
                #pragma unroll
                for (int e = 0; e < EPW_A; e++) {
                    float* s = scr + e * A_STRIDE;
                    float aa = P1[0][e] + __shfl_xor_sync(FULLMASK, P1[0][e], 16);
                    float bb = P2[0][e] + __shfl_xor_sync(FULLMASK, P2[0][e], 16);
                    float cc = P1[1][e] + __shfl_xor_sync(FULLMASK, P1[1][e], 16);
                    float dd = P2[1][e] + __shfl_xor_sync(FULLMASK, P2[1][e], 16);
                    float za = (l < 16) ? aa : bb;
                    float zc = (l < 16) ? cc : dd;
                    za += __shfl_xor_sync(FULLMASK, za, 8);
                    zc += __shfl_xor_sync(FULLMASK, zc, 8);
                    float z = ((l & 8) == 0) ? za : zc;
                    z += __shfl_xor_sync(FULLMASK, z, 4);
                    z += __shfl_xor_sync(FULLMASK, z, 2);
                    z += __shfl_xor_sync(FULLMASK, z, 1);
                    if      (l == 0)  s[ASC_WH + t]      = z;
                    else if (l == 8)  s[ASC_WH + t + 1]  = z;
                    else if (l == 16) s[ASC_WH + 10 + t] = z;
                    else if (l == 24) s[ASC_WH + 11 + t] = z;
                }
            }
        }
        __syncwarp();

        // ---- stage 2: attention softmaxes ----
        #pragma unroll
        for (int e = 0; e < EPW_A; e++) {
            float* s = scr + e * A_STRIDE;
            if (l < 10) {
                float ev[5]; float m = -1e30f;
                const float w1 = s[ASC_WH + l];
                if (l < 5) {
                    #pragma unroll
                    for (int c = 0; c < 5; c++) {
                        float v = leakyf(w1 + s[ASC_WH + 15 + c]);
                        ev[c] = v; m = fmaxf(m, v);
                    }
                } else {
                    #pragma unroll
                    for (int c = 0; c < 5; c++) {
                        float v = leakyf(w1 + s[ASC_WH + 10 + c]);
                        ev[c] = v; m = fmaxf(m, v);
                    }
                }
                float ssum = 0.f;
                #pragma unroll
                for (int c = 0; c < 5; c++) { ev[c] = __expf(ev[c] - m); ssum += ev[c]; }
                const float inv = __fdividef(1.0f, ssum);
                if (l < 5) {
                    #pragma unroll
                    for (int c = 0; c < 5; c++) s[ASC_ATT + l * 12 + c] = ev[c] * inv;
                } else {
                    const int q = l - 5;
                    #pragma unroll
                    for (int c = 0; c < 5; c++) s[ASC_ATT + c * 12 + 5 + q] = ev[c] * inv;
                }
            } else if (l < 20) {
                const int i = l - 10;
                s[ASC_ATT + (i >> 1) * 12 + 10 + (i & 1)] = 0.f;
            }
        }
        __syncwarp();

        // ---- stage 3: hp1 ----
        {
            const ulonglong2 w1a = lp4(sm + A_WO1T + l * 12);
            const ulonglong2 w1b = lp4(sm + A_WO1T + l * 12 + 4);
            const ulonglong2 w1c = lp4(sm + A_WO1T + l * 12 + 8);
            const float bo1v = sm[A_BO1 + l];
            #pragma unroll
            for (int k = 0; k < 5; k++) {
                #pragma unroll
                for (int e = 0; e < EPW_A; e++) {
                    float* s = scr + e * A_STRIDE;
                    ulonglong2 t0 = lp4(s + ASC_ATT + k * 12);
                    ulonglong2 t1 = lp4(s + ASC_ATT + k * 12 + 4);
                    ulonglong2 t2 = lp4(s + ASC_ATT + k * 12 + 8);
                    u64 acc = 0;
                    dfma2(acc, t0.x, w1a.x); dfma2(acc, t0.y, w1a.y);
                    dfma2(acc, t1.x, w1b.x); dfma2(acc, t1.y, w1b.y);
                    dfma2(acc, t2.x, w1c.x); dfma2(acc, t2.y, w1c.y);
                    s[ASC_U1 + k * 32 + l] = leakyf(bo1v + f2sum(acc));
                }
            }
        }
        __syncwarp();

        // ---- stage 4: hp2 ----
        {
            ulonglong2 w2[8];
            #pragma unroll
            for (int q = 0; q < 8; q++) w2[q] = lp4(sm + A_WO2T + (l & 15) * 36 + q * 4);
            const float bo2v = sm[A_BO2 + (l & 15)];
            #pragma unroll
            for (int k = 0; k < 3; k++) {
                const int idx = l + 32 * k;
                const bool act = idx < 80;
                const int r = idx >> 4;
                #pragma unroll
                for (int e = 0; e < EPW_A; e++) {
                    float* s = scr + e * A_STRIDE;
                    const float* hp = s + ASC_U1 + r * 32;
                    u64 acc = 0;
                    #pragma unroll
                    for (int q = 0; q < 8; q++) {
                        ulonglong2 hv = lp4(hp + q * 4);
                        dfma2(acc, hv.x, w2[q].x);
                        dfma2(acc, hv.y, w2[q].y);
                    }
                    if (act) s[ASC_HP2 + idx] = leakyf(bo2v + f2sum(acc));
                }
            }
        }
        __syncwarp();

        // ---- stage 5: hp3 + softmax -> g_obs_out ----
        {
            ulonglong2 w3a = lp4(sm + A_WO3), w3b = lp4(sm + A_WO3 + 8);
            const float bo3v = sm[A_BO3];
            #pragma unroll
            for (int e = 0; e < EPW_A; e++) {
                float* s = scr + e * A_STRIDE;
                const int r = (l < 5) ? l : 4;
                const float* h2p = s + ASC_HP2 + r * 16;
                ulonglong2 p0 = lp4(h2p), p1 = lp4(h2p + 8);
                u64 acc = 0;
                dfma2(acc, p0.x, w3a.x); dfma2(acc, p0.y, w3a.y);
                dfma2(acc, p1.x, w3b.x); dfma2(acc, p1.y, w3b.y);
                const float v = leakyf(bo3v + f2sum(acc));
                const float v0 = __shfl_sync(FULLMASK, v, 0);
                const float v1 = __shfl_sync(FULLMASK, v, 1);
                const float v2 = __shfl_sync(FULLMASK, v, 2);
                const float v3 = __shfl_sync(FULLMASK, v, 3);
                const float v4 = __shfl_sync(FULLMASK, v, 4);
                const float m  = fmaxf(fmaxf(fmaxf(v0, v1), fmaxf(v2, v3)), v4);
                const float ssum = __expf(v0 - m) + __expf(v1 - m) + __expf(v2 - m)
                                 + __expf(v3 - m) + __expf(v4 - m);
                if (l < 5)
                    g_obs_out[(size_t)(e0 + e) * 5 + l] = __fdividef(__expf(v - m), ssum);
            }
        }
        __syncwarp();
    }
}

// ============================================================================
// Kernel B: stages 6-7 — 16 warps x EPW 8, split-gate GRU passes
// ============================================================================
__global__ __launch_bounds__(THREADS_B, 1)
void atom_rnn_gru(
    const float* __restrict__ obs,    const float* __restrict__ hidden,
    const float* __restrict__ w_fc1,  const float* __restrict__ b_fc1,
    const float* __restrict__ w_ih,   const float* __restrict__ w_hh,
    const float* __restrict__ b_ih,   const float* __restrict__ b_hh,
    const float* __restrict__ w_fc2,  const float* __restrict__ b_fc2,
    float* __restrict__ out)
{
    extern __shared__ float sm[];
    const int tid = threadIdx.x;
    const int wid = tid >> 5;
    const int l   = tid & 31;

    // ---- weight staging ----
    for (int i = tid; i < 5760; i += THREADS_B) {
        int c = i >> 6, j = i & 63;
        sm[B_WFC1T + j * 92 + c] = w_fc1[i];
    }
    for (int i = tid; i < 128; i += THREADS_B) sm[B_WFC1T + (i >> 1) * 92 + 90 + (i & 1)] = 0.f;
    for (int i = tid; i < 192 * 64; i += THREADS_B) {
        int g = i >> 6, c = i & 63;
        sm[B_WIHT + g * 68 + c] = w_ih[i];
        sm[B_WHHT + g * 68 + c] = w_hh[i];
    }
    for (int i = tid; i < 192; i += THREADS_B) { sm[B_BIH + i] = b_ih[i]; sm[B_BHH + i] = b_hh[i]; }
    for (int i = tid; i < 320; i += THREADS_B) sm[B_WFC2 + i] = w_fc2[i];
    if (tid < 64) sm[B_BFC1 + tid] = b_fc1[tid];
    if (tid < 5)  sm[B_BFC2 + tid] = b_fc2[tid];
    __syncthreads();

    float* scr = sm + B_SCR + (wid * EPW_B) * B_STRIDE;
    const int stride = gridDim.x * WARPS_B * EPW_B;

    const float blo = sm[B_BFC1 + l], bhi = sm[B_BFC1 + 32 + l];

    for (int e0 = (blockIdx.x * WARPS_B + wid) * EPW_B; e0 < BATCH; e0 += stride) {

        // ---- load obs + obs_out + hidden ----
        #pragma unroll
        for (int e = 0; e < EPW_B; e++) {
            const float* op = obs    + (size_t)(e0 + e) * 85;
            const float* hp = hidden + (size_t)(e0 + e) * 64;
            float* s = scr + e * B_STRIDE;
            #pragma unroll
            for (int i = 0; i < 3; i++) {
                int idx = l + i * 32;
                if (idx < 85) s[BSC_OBS + idx] = op[idx];
            }
            if (l < 5) s[BSC_OBS + 85 + l] = g_obs_out[(size_t)(e0 + e) * 5 + l];
            if (l == 0) { s[BSC_OBS + 90] = 0.f; s[BSC_OBS + 91] = 0.f; }
            s[BSC_HIN + l]      = hp[l];
            s[BSC_HIN + 32 + l] = hp[l + 32];
        }
        __syncwarp();

        // ---- stage 6: x = relu(obs_comb @ w_fc1 + b_fc1); X overlays OBS ----
        {
            u64 xlo2[EPW_B], xhi2[EPW_B];
            #pragma unroll
            for (int e = 0; e < EPW_B; e++) { xlo2[e] = 0; xhi2[e] = 0; }
            const float* wloP = sm + B_WFC1T + l * 92;
            const float* whiP = sm + B_WFC1T + (l + 32) * 92;
            #pragma unroll 23
            for (int cq = 0; cq < 23; cq++) {
                const ulonglong2 wl = lp4(wloP + cq * 4);
                const ulonglong2 wh = lp4(whiP + cq * 4);
                #pragma unroll
                for (int e = 0; e < EPW_B; e++) {
                    const ulonglong2 v = lp4(scr + e * B_STRIDE + BSC_OBS + cq * 4);
                    dfma2(xlo2[e], v.x, wl.x); dfma2(xlo2[e], v.y, wl.y);
                    dfma2(xhi2[e], v.x, wh.x); dfma2(xhi2[e], v.y, wh.y);
                }
            }
            __syncwarp();   // all OBS reads complete before X overwrites
            #pragma unroll
            for (int e = 0; e < EPW_B; e++) {
                scr[e * B_STRIDE + BSC_X + l]      = fmaxf(blo + f2sum(xlo2[e]), 0.f);
                scr[e * B_STRIDE + BSC_X + 32 + l] = fmaxf(bhi + f2sum(xhi2[e]), 0.f);
            }
        }
        __syncwarp();

        // ---- stage 7: GRU (two h2 passes x two gate passes) + q projection ----
        {
            float hnew0[EPW_B];   // h2=0 hnew, kept for q projection

            #pragma unroll
            for (int h2 = 0; h2 < 2; h2++) {
                const int g0 = h2 * 32 + l;
                const float* wiB = sm + B_WIHT + g0 * 68;
                const float* whB = sm + B_WHHT + g0 * 68;

                // --- gate pass 1: r and z ---
                float rr[EPW_B], zz[EPW_B];
                {
                    u64 sr2[EPW_B], sz2[EPW_B];
                    #pragma unroll
                    for (int e = 0; e < EPW_B; e++) { sr2[e] = 0; sz2[e] = 0; }
                    #pragma unroll 4
                    for (int cq = 0; cq < 16; cq++) {
                        const ulonglong2 wir = lp4(wiB + cq * 4);
                        const ulonglong2 wiz = lp4(wiB + 64 * 68 + cq * 4);
                        const ulonglong2 whr = lp4(whB + cq * 4);
                        const ulonglong2 whz = lp4(whB + 64 * 68 + cq * 4);
                        #pragma unroll
                        for (int e = 0; e < EPW_B; e++) {
                            const ulonglong2 xv = lp4(scr + e * B_STRIDE + BSC_X   + cq * 4);
                            const ulonglong2 hv = lp4(scr + e * B_STRIDE + BSC_HIN + cq * 4);
                            dfma2(sr2[e], xv.x, wir.x); dfma2(sr2[e], xv.y, wir.y);
                            dfma2(sr2[e], hv.x, whr.x); dfma2(sr2[e], hv.y, whr.y);
                            dfma2(sz2[e], xv.x, wiz.x); dfma2(sz2[e], xv.y, wiz.y);
                            dfma2(sz2[e], hv.x, whz.x); dfma2(sz2[e], hv.y, whz.y);
                        }
                    }
                    const float br = sm[B_BIH + g0]      + sm[B_BHH + g0];
                    const float bz = sm[B_BIH + 64 + g0] + sm[B_BHH + 64 + g0];
                    #pragma unroll
                    for (int e = 0; e < EPW_B; e++) {
                        rr[e] = sigmoidf_(br + f2sum(sr2[e]));
                        zz[e] = sigmoidf_(bz + f2sum(sz2[e]));
                    }
                }

                // --- gate pass 2: n, then epilogue ---
                {
                    u64 gn2[EPW_B], hn2[EPW_B];
                    #pragma unroll
                    for (int e = 0; e < EPW_B; e++) { gn2[e] = 0; hn2[e] = 0; }
                    #pragma unroll 4
                    for (int cq = 0; cq < 16; cq++) {
                        const ulonglong2 win = lp4(wiB + 128 * 68 + cq * 4);
                        const ulonglong2 whn = lp4(whB + 128 * 68 + cq * 4);
                        #pragma unroll
                        for (int e = 0; e < EPW_B; e++) {
                            const ulonglong2 xv = lp4(scr + e * B_STRIDE + BSC_X   + cq * 4);
                            const ulonglong2 hv = lp4(scr + e * B_STRIDE + BSC_HIN + cq * 4);
                            dfma2(gn2[e], xv.x, win.x); dfma2(gn2[e], xv.y, win.y);
                            dfma2(hn2[e], hv.x, whn.x); dfma2(hn2[e], hv.y, whn.y);
                        }
                    }
                    const float bgn = sm[B_BIH + 128 + g0];
                    const float bhn = sm[B_BHH + 128 + g0];
                    const float wq0 = sm[B_WFC2 + g0 * 5 + 0];
                    const float wq1 = sm[B_WFC2 + g0 * 5 + 1];
                    const float wq2 = sm[B_WFC2 + g0 * 5 + 2];
                    const float wq3 = sm[B_WFC2 + g0 * 5 + 3];
                    const float wq4 = sm[B_WFC2 + g0 * 5 + 4];
                    #pragma unroll
                    for (int e = 0; e < EPW_B; e++) {
                        const float nn = tanhf_((bgn + f2sum(gn2[e])) + rr[e] * (bhn + f2sum(hn2[e])));
                        const float hprev = scr[e * B_STRIDE + BSC_HIN + g0];
                        const float hnew  = (1.0f - zz[e]) * nn + zz[e] * hprev;
                        out[HOFF + (size_t)(e0 + e) * 64 + g0] = hnew;
                        if (h2 == 0) {
                            hnew0[e] = hnew;
                        } else {
                            // q projection + packed reduction for this element
                            const int g00 = l;   // h2=0 row for this lane
                            float qp0 = hnew0[e] * sm[B_WFC2 + g00 * 5 + 0] + hnew * wq0;
                            float qp1 = hnew0[e] * sm[B_WFC2 + g00 * 5 + 1] + hnew * wq1;
                            float qp2 = hnew0[e] * sm[B_WFC2 + g00 * 5 + 2] + hnew * wq2;
                            float qp3 = hnew0[e] * sm[B_WFC2 + g00 * 5 + 3] + hnew * wq3;
                            float qp4 = hnew0[e] * sm[B_WFC2 + g00 * 5 + 4] + hnew * wq4;
                            float a0 = qp0 + __shfl_xor_sync(FULLMASK, qp0, 16);
                            float a1 = qp1 + __shfl_xor_sync(FULLMASK, qp1, 16);
                            float a2 = qp2 + __shfl_xor_sync(FULLMASK, qp2, 16);
                            float a3 = qp3 + __shfl_xor_sync(FULLMASK, qp3, 16);
                            float a4 = qp4 + __shfl_xor_sync(FULLMASK, qp4, 16);
                            float z1 = (l < 16) ? a0 : a1;
                            float z2 = (l < 16) ? a2 : a3;
                            z1 += __shfl_xor_sync(FULLMASK, z1, 8);
                            z2 += __shfl_xor_sync(FULLMASK, z2, 8);
                            a4 += __shfl_xor_sync(FULLMASK, a4, 8);
                            float w = (l & 8) ? z2 : z1;
                            w  += __shfl_xor_sync(FULLMASK, w, 4);
                            w  += __shfl_xor_sync(FULLMASK, w, 2);
                            w  += __shfl_xor_sync(FULLMASK, w, 1);
                            a4 += __shfl_xor_sync(FULLMASK, a4, 4);
                            a4 += __shfl_xor_sync(FULLMASK, a4, 2);
                            a4 += __shfl_xor_sync(FULLMASK, a4, 1);
                            float* qo = out + (size_t)(e0 + e) * 5;
                            if (l == 0) {
                                qo[0] = w  + sm[B_BFC2 + 0];
                                qo[4] = a4 + sm[B_BFC2 + 4];
                            } else if (l == 8) {
                                qo[2] = w + sm[B_BFC2 + 2];
                            } else if (l == 16) {
                                qo[1] = w + sm[B_BFC2 + 1];
                            } else if (l == 24) {
                                qo[3] = w + sm[B_BFC2 + 3];
                            }
                        }
                    }
                }
            }
        }
        __syncwarp();
    }
}

extern "C" void kernel_launch(void* const* d_in, const int* in_sizes, int n_in,
                              void* d_out, int out_size) {
    (void)in_sizes; (void)n_in; (void)out_size;
    int dev = 0;
    cudaGetDevice(&dev);
    int nsm = 148;
    cudaDeviceGetAttribute(&nsm, cudaDevAttrMultiProcessorCount, dev);
    cudaFuncSetAttribute(atom_rnn_attn, cudaFuncAttributeMaxDynamicSharedMemorySize, SMEM_A);
    cudaFuncSetAttribute(atom_rnn_gru,  cudaFuncAttributeMaxDynamicSharedMemorySize, SMEM_B);

    atom_rnn_attn<<<nsm, THREADS_A, SMEM_A>>>(
        (const float*)d_in[0],
        (const float*)d_in[2],  (const float*)d_in[3],
        (const float*)d_in[4],  (const float*)d_in[5],
        (const float*)d_in[6],  (const float*)d_in[7],
        (const float*)d_in[8],  (const float*)d_in[9],
        (const float*)d_in[10], (const float*)d_in[11],
        (const float*)d_in[12], (const float*)d_in[13],
        (const float*)d_in[14], (const float*)d_in[15]);

    atom_rnn_gru<<<nsm, THREADS_B, SMEM_B>>>(
        (const float*)d_in[0],  (const float*)d_in[1],
        (const float*)d_in[16], (const float*)d_in[17],
        (const float*)d_in[18], (const float*)d_in[19],
        (const float*)d_in[20], (const float*)d_in[21],
        (const float*)d_in[22], (const float*)d_in[23],
        (float*)d_out);
}

// round 12
// speedup vs baseline: 1.0117x; 1.0117x over previous
#include <cuda_runtime.h>

#define FULLMASK 0xffffffffu

typedef unsigned long long u64;

constexpr int BATCH  = 65536;
constexpr int HOFF   = BATCH * 5;      // h output offset (q first, then h)

// ===================== kernel A (attention, stages 0-5) =====================
constexpr int WARPS_A   = 16;
constexpr int EPW_A     = 4;
constexpr int THREADS_A = WARPS_A * 32;    // 512

constexpr int A_WINT  = 0;       // 3 * 64 rows * 12 = 2304
constexpr int A_BIN   = 2304;    // 192
constexpr int A_WA    = 2496;    // 128
constexpr int A_WO1T  = 2624;    // 384
constexpr int A_BO1   = 3008;    // 32
constexpr int A_WO2T  = 3040;    // 576
constexpr int A_BO2   = 3616;    // 16
constexpr int A_WO3   = 3632;    // 16
constexpr int A_BO3   = 3648;    // 4
constexpr int A_SCR   = 3652;

constexpr int ASC_OBS = 0;    // 88 (obs 85 + pad)
constexpr int ASC_U1  = 88;   // 160: HP1 5x32
constexpr int ASC_U2  = 248;  // 84: WH 20 | ATT 5x12 @+24 | HP2 80
constexpr int ASC_WH  = ASC_U2;
constexpr int ASC_ATT = ASC_U2 + 24;
constexpr int ASC_HP2 = ASC_U2;
constexpr int A_STRIDE = 336;

constexpr int SMEM_A = (A_SCR + WARPS_A * EPW_A * A_STRIDE) * 4;   // 100624 B

// ===================== kernel B (fc1 + GRU + q, stages 6-7) =================
constexpr int WARPS_B   = 16;
constexpr int EPW_B     = 8;
constexpr int THREADS_B = WARPS_B * 32;    // 512

constexpr int B_WFC1T = 0;       // 64 rows * 92 = 5888
constexpr int B_BFC1  = 5888;    // 64
constexpr int B_WFC2  = 5952;    // 320
constexpr int B_BFC2  = 6272;    // 8
constexpr int B_WIHT  = 6280;    // 192 rows * 68 = 13056
constexpr int B_BIH   = 19336;   // 192
constexpr int B_WHHT  = 19528;   // 13056
constexpr int B_BHH   = 32584;   // 192
constexpr int B_SCR   = 32776;

// X aliases OBS[0..63] (OBS dead after stage-6 reads, which precede X stores)
constexpr int BSC_OBS = 0;    // 92 (obs 85 + obs_out 5 + pads 90,91=0)
constexpr int BSC_X   = 0;    // 64, overlays OBS
constexpr int BSC_HIN = 92;   // 64
constexpr int B_STRIDE = 160;

constexpr int SMEM_B = (B_SCR + WARPS_B * EPW_B * B_STRIDE) * 4;   // 213024 B

__device__ float g_obs_out[BATCH * 5];

__device__ __forceinline__ float leakyf(float x)    { return fmaxf(x, 0.01f * x); }
__device__ __forceinline__ float sigmoidf_(float x) { return 1.0f / (1.0f + __expf(-x)); }
__device__ __forceinline__ float tanhf_(float x)    { float t = __expf(2.0f * x); return 1.0f - __fdividef(2.0f, t + 1.0f); }

__device__ __forceinline__ void dfma2(u64& acc, u64 v, u64 w) {
    asm("fma.rn.f32x2 %0, %1, %2, %0;" : "+l"(acc) : "l"(v), "l"(w));
}
__device__ __forceinline__ float f2sum(u64 a) {
    float lo, hi;
    asm("mov.b64 {%0, %1}, %2;" : "=f"(lo), "=f"(hi) : "l"(a));
    return lo + hi;
}
__device__ __forceinline__ ulonglong2 lp4(const float* p) {
    return *reinterpret_cast<const ulonglong2*>(p);
}

// ============================================================================
// Kernel A: stages 0-5 -> g_obs_out   (16 warps x EPW 4 — proven config)
// ============================================================================
__global__ __launch_bounds__(THREADS_A, 1)
void atom_rnn_attn(
    const float* __restrict__ obs,
    const float* __restrict__ w_in0,  const float* __restrict__ b_in0,
    const float* __restrict__ w_in1,  const float* __restrict__ b_in1,
    const float* __restrict__ w_in2,  const float* __restrict__ b_in2,
    const float* __restrict__ W,      const float* __restrict__ a,
    const float* __restrict__ w_o1,   const float* __restrict__ b_o1,
    const float* __restrict__ w_o2,   const float* __restrict__ b_o2,
    const float* __restrict__ w_o3,   const float* __restrict__ b_o3)
{
    extern __shared__ float sm[];
    const int tid = threadIdx.x;
    const int wid = tid >> 5;
    const int l   = tid & 31;

    // ---- weight staging ----
    for (int i = tid; i < 512; i += THREADS_A) {
        int f = i >> 6, r = i & 63;
        sm[A_WINT +        r * 12 + f] = w_in0[i];
        sm[A_WINT +  768 + r * 12 + f] = w_in1[i];
        sm[A_WINT + 1536 + r * 12 + f] = w_in2[i];
    }
    for (int i = tid; i < 320; i += THREADS_A) {
        int c = i >> 5, o = i & 31;
        sm[A_WO1T + o * 12 + c] = w_o1[i];
    }
    if (tid < 64) sm[A_WO1T + (tid >> 1) * 12 + 10 + (tid & 1)] = 0.f;
    for (int i = tid; i < 512; i += THREADS_A) {
        int c = i >> 4, o = i & 15;
        sm[A_WO2T + o * 36 + c] = w_o2[i];
    }
    if (tid < 64) {
        sm[A_BIN + tid]       = b_in0[tid];
        sm[A_BIN + 64 + tid]  = b_in1[tid];
        sm[A_BIN + 128 + tid] = b_in2[tid];
        float a0 = 0.f, a1 = 0.f;                  // fold W @ a
        for (int i = 0; i < 64; i++) {
            float w = W[i * 64 + tid];
            a0 += w * a[i];
            a1 += w * a[64 + i];
        }
        sm[A_WA + tid]      = a0;
        sm[A_WA + 64 + tid] = a1;
    }
    if (tid < 32) sm[A_BO1 + tid] = b_o1[tid];
    if (tid < 16) { sm[A_BO2 + tid] = b_o2[tid]; sm[A_WO3 + tid] = w_o3[tid]; }
    if (tid == 0) sm[A_BO3] = b_o3[0];
    __syncthreads();

    float* scr = sm + A_SCR + (wid * EPW_A) * A_STRIDE;
    const int stride = gridDim.x * WARPS_A * EPW_A;

    const float wa0l = sm[A_WA + l],      wa0h = sm[A_WA + 32 + l];
    const float wa1l = sm[A_WA + 64 + l], wa1h = sm[A_WA + 96 + l];

    for (int e0 = (blockIdx.x * WARPS_A + wid) * EPW_A; e0 < BATCH; e0 += stride) {

        // ---- stage 0: load obs ----
        #pragma unroll
        for (int e = 0; e < EPW_A; e++) {
            const float* op = obs + (size_t)(e0 + e) * 85;
            float* s = scr + e * A_STRIDE;
            #pragma unroll
            for (int i = 0; i < 3; i++) {
                int idx = l + i * 32;
                if (idx < 85) s[ASC_OBS + idx] = op[idx];
            }
        }
        __syncwarp();

        // ---- stage 1: token nets (hoisted weights, packed) -> WH[0..19] ----
        {
            ulonglong2 wlA, wlB, whA, whB; float blo, bhi;
            {
                const float* wb = sm + A_WINT;   // net 0
                wlA = lp4(wb + l * 12);        wlB = lp4(wb + l * 12 + 4);
                whA = lp4(wb + (l + 32) * 12); whB = lp4(wb + (l + 32) * 12 + 4);
                blo = sm[A_BIN + l]; bhi = sm[A_BIN + 32 + l];
            }
            #pragma unroll
            for (int tp = 0; tp < 5; tp++) {
                float P1[2][EPW_A], P2[2][EPW_A];
                #pragma unroll
                for (int half = 0; half < 2; half++) {
                    const int t = 2 * tp + half;
                    if (t == 5) {
                        const float* wb = sm + A_WINT + 768;   // net 1
                        wlA = lp4(wb + l * 12);        wlB = lp4(wb + l * 12 + 4);
                        whA = lp4(wb + (l + 32) * 12); whB = lp4(wb + (l + 32) * 12 + 4);
                        blo = sm[A_BIN + 64 + l]; bhi = sm[A_BIN + 96 + l];
                    }
                    if (t == 9) {
                        const float* wb = sm + A_WINT + 1536;  // net 2
                        wlA = lp4(wb + l * 12);        wlB = lp4(wb + l * 12 + 4);
                        whA = lp4(wb + (l + 32) * 12); whB = lp4(wb + (l + 32) * 12 + 4);
                        blo = sm[A_BIN + 128 + l]; bhi = sm[A_BIN + 160 + l];
                    }
                    #pragma unroll
                    for (int e = 0; e < EPW_A; e++) {
                        const float* s = scr + e * A_STRIDE;
                        ulonglong2 v0 = lp4(s + ASC_OBS + t * 8 + 4);
                        ulonglong2 v1 = (t == 9) ? lp4(s + ASC_OBS) : lp4(s + ASC_OBS + t * 8 + 8);
                        u64 accl = 0, acch = 0;
                        dfma2(accl, v0.x, wlA.x); dfma2(accl, v0.y, wlA.y);
                        dfma2(accl, v1.x, wlB.x); dfma2(accl, v1.y, wlB.y);
                        dfma2(acch, v0.x, whA.x); dfma2(acch, v0.y, whA.y);
                        dfma2(acch, v1.x, whB.x); dfma2(acch, v1.y, whB.y);
                        float hl = leakyf(blo + f2sum(accl));
                        float hh = leakyf(bhi + f2sum(acch));
                        P1[half][e] = hl * wa0l + hh * wa0h;
                        P2[half][e] = hl * wa1l + hh * wa1h;
                    }
                }
                const int t = 2 * tp;
                #pragma unroll
                for (int e = 0; e < EPW_A; e++) {
                    float* s = scr + e * A_STRIDE;
                    float aa = P1[0][e] + __shfl_xor_sync(FULLMASK, P1[0][e], 16);
                    float bb = P2[0][e] + __shfl_xor_sync(FULLMASK, P2[0][e], 16);
                    float cc = P1[1][e] + __shfl_xor_sync(FULLMASK, P1[1][e], 16);
                    float dd = P2[1][e] + __shfl_xor_sync(FULLMASK, P2[1][e], 16);
                    float za = (l < 16) ? aa : bb;
                    float zc = (l < 16) ? cc : dd;
                    za += __shfl_xor_sync(FULLMASK, za, 8);
                    zc += __shfl_xor_sync(FULLMASK, zc, 8);
                    float z = ((l & 8) == 0) ? za : zc;
                    z += __shfl_xor_sync(FULLMASK, z, 4);
                    z += __shfl_xor_sync(FULLMASK, z, 2);
                    z += __shfl_xor_sync(FULLMASK, z, 1);
                    if      (l == 0)  s[ASC_WH + t]      = z;
                    else if (l == 8)  s[ASC_WH + t + 1]  = z;
                    else if (l == 16) s[ASC_WH + 10 + t] = z;
                    else if (l == 24) s[ASC_WH + 11 + t] = z;
                }
            }
        }
        __syncwarp();

        // ---- stage 2: attention softmaxes ----
        #pragma unroll
        for (int e = 0; e < EPW_A; e++) {
            float* s = scr + e * A_STRIDE;
            if (l < 10) {
                float ev[5]; float m = -1e30f;
                const float w1 = s[ASC_WH + l];
                if (l < 5) {
                    #pragma unroll
                    for (int c = 0; c < 5; c++) {
                        float v = leakyf(w1 + s[ASC_WH + 15 + c]);
                        ev[c] = v; m = fmaxf(m, v);
                    }
                } else {
                    #pragma unroll
                    for (int c = 0; c < 5; c++) {
                        float v = leakyf(w1 + s[ASC_WH + 10 + c]);
                        ev[c] = v; m = fmaxf(m, v);
                    }
                }
                float ssum = 0.f;
                #pragma unroll
                for (int c = 0; c < 5; c++) { ev[c] = __expf(ev[c] - m); ssum += ev[c]; }
                const float inv = __fdividef(1.0f, ssum);
                if (l < 5) {
                    #pragma unroll
                    for (int c = 0; c < 5; c++) s[ASC_ATT + l * 12 + c] = ev[c] * inv;
                } else {
                    const int q = l - 5;
                    #pragma unroll
                    for (int c = 0; c < 5; c++) s[ASC_ATT + c * 12 + 5 + q] = ev[c] * inv;
                }
            } else if (l < 20) {
                const int i = l - 10;
                s[ASC_ATT + (i >> 1) * 12 + 10 + (i & 1)] = 0.f;
            }
        }
        __syncwarp();

        // ---- stage 3: hp1 ----
        {
            const ulonglong2 w1a = lp4(sm + A_WO1T + l * 12);
            const ulonglong2 w1b = lp4(sm + A_WO1T + l * 12 + 4);
            const ulonglong2 w1c = lp4(sm + A_WO1T + l * 12 + 8);
            const float bo1v = sm[A_BO1 + l];
            #pragma unroll
            for (int k = 0; k < 5; k++) {
                #pragma unroll
                for (int e = 0; e < EPW_A; e++) {
                    float* s = scr + e * A_STRIDE;
                    ulonglong2 t0 = lp4(s + ASC_ATT + k * 12);
                    ulonglong2 t1 = lp4(s + ASC_ATT + k * 12 + 4);
                    ulonglong2 t2 = lp4(s + ASC_ATT + k * 12 + 8);
                    u64 acc = 0;
                    dfma2(acc, t0.x, w1a.x); dfma2(acc, t0.y, w1a.y);
                    dfma2(acc, t1.x, w1b.x); dfma2(acc, t1.y, w1b.y);
                    dfma2(acc, t2.x, w1c.x); dfma2(acc, t2.y, w1c.y);
                    s[ASC_U1 + k * 32 + l] = leakyf(bo1v + f2sum(acc));
                }
            }
        }
        __syncwarp();

        // ---- stage 4: hp2 ----
        {
            ulonglong2 w2[8];
            #pragma unroll
            for (int q = 0; q < 8; q++) w2[q] = lp4(sm + A_WO2T + (l & 15) * 36 + q * 4);
            const float bo2v = sm[A_BO2 + (l & 15)];
            #pragma unroll
            for (int k = 0; k < 3; k++) {
                const int idx = l + 32 * k;
                const bool act = idx < 80;
                const int r = idx >> 4;
                #pragma unroll
                for (int e = 0; e < EPW_A; e++) {
                    float* s = scr + e * A_STRIDE;
                    const float* hp = s + ASC_U1 + r * 32;
                    u64 acc = 0;
                    #pragma unroll
                    for (int q = 0; q < 8; q++) {
                        ulonglong2 hv = lp4(hp + q * 4);
                        dfma2(acc, hv.x, w2[q].x);
                        dfma2(acc, hv.y, w2[q].y);
                    }
                    if (act) s[ASC_HP2 + idx] = leakyf(bo2v + f2sum(acc));
                }
            }
        }
        __syncwarp();

        // ---- stage 5: hp3 + softmax -> g_obs_out ----
        {
            ulonglong2 w3a = lp4(sm + A_WO3), w3b = lp4(sm + A_WO3 + 8);
            const float bo3v = sm[A_BO3];
            #pragma unroll
            for (int e = 0; e < EPW_A; e++) {
                float* s = scr + e * A_STRIDE;
                const int r = (l < 5) ? l : 4;
                const float* h2p = s + ASC_HP2 + r * 16;
                ulonglong2 p0 = lp4(h2p), p1 = lp4(h2p + 8);
                u64 acc = 0;
                dfma2(acc, p0.x, w3a.x); dfma2(acc, p0.y, w3a.y);
                dfma2(acc, p1.x, w3b.x); dfma2(acc, p1.y, w3b.y);
                const float v = leakyf(bo3v + f2sum(acc));
                const float v0 = __shfl_sync(FULLMASK, v, 0);
                const float v1 = __shfl_sync(FULLMASK, v, 1);
                const float v2 = __shfl_sync(FULLMASK, v, 2);
                const float v3 = __shfl_sync(FULLMASK, v, 3);
                const float v4 = __shfl_sync(FULLMASK, v, 4);
                const float m  = fmaxf(fmaxf(fmaxf(v0, v1), fmaxf(v2, v3)), v4);
                const float ssum = __expf(v0 - m) + __expf(v1 - m) + __expf(v2 - m)
                                 + __expf(v3 - m) + __expf(v4 - m);
                if (l < 5)
                    g_obs_out[(size_t)(e0 + e) * 5 + l] = __fdividef(__expf(v - m), ssum);
            }
        }
        __syncwarp();
    }
}

// ============================================================================
// Kernel B: stages 6-7 — 16 warps x EPW 8, single-pass gates (R8 structure)
// ============================================================================
__global__ __launch_bounds__(THREADS_B, 1)
void atom_rnn_gru(
    const float* __restrict__ obs,    const float* __restrict__ hidden,
    const float* __restrict__ w_fc1,  const float* __restrict__ b_fc1,
    const float* __restrict__ w_ih,   const float* __restrict__ w_hh,
    const float* __restrict__ b_ih,   const float* __restrict__ b_hh,
    const float* __restrict__ w_fc2,  const float* __restrict__ b_fc2,
    float* __restrict__ out)
{
    extern __shared__ float sm[];
    const int tid = threadIdx.x;
    const int wid = tid >> 5;
    const int l   = tid & 31;

    // ---- weight staging ----
    for (int i = tid; i < 5760; i += THREADS_B) {
        int c = i >> 6, j = i & 63;
        sm[B_WFC1T + j * 92 + c] = w_fc1[i];
    }
    for (int i = tid; i < 128; i += THREADS_B) sm[B_WFC1T + (i >> 1) * 92 + 90 + (i & 1)] = 0.f;
    for (int i = tid; i < 192 * 64; i += THREADS_B) {
        int g = i >> 6, c = i & 63;
        sm[B_WIHT + g * 68 + c] = w_ih[i];
        sm[B_WHHT + g * 68 + c] = w_hh[i];
    }
    for (int i = tid; i < 192; i += THREADS_B) { sm[B_BIH + i] = b_ih[i]; sm[B_BHH + i] = b_hh[i]; }
    for (int i = tid; i < 320; i += THREADS_B) sm[B_WFC2 + i] = w_fc2[i];
    if (tid < 64) sm[B_BFC1 + tid] = b_fc1[tid];
    if (tid < 5)  sm[B_BFC2 + tid] = b_fc2[tid];
    __syncthreads();

    float* scr = sm + B_SCR + (wid * EPW_B) * B_STRIDE;
    const int stride = gridDim.x * WARPS_B * EPW_B;

    const float blo = sm[B_BFC1 + l], bhi = sm[B_BFC1 + 32 + l];

    for (int e0 = (blockIdx.x * WARPS_B + wid) * EPW_B; e0 < BATCH; e0 += stride) {

        // ---- load obs + obs_out + hidden ----
        #pragma unroll
        for (int e = 0; e < EPW_B; e++) {
            const float* op = obs    + (size_t)(e0 + e) * 85;
            const float* hp = hidden + (size_t)(e0 + e) * 64;
            float* s = scr + e * B_STRIDE;
            #pragma unroll
            for (int i = 0; i < 3; i++) {
                int idx = l + i * 32;
                if (idx < 85) s[BSC_OBS + idx] = op[idx];
            }
            if (l < 5) s[BSC_OBS + 85 + l] = g_obs_out[(size_t)(e0 + e) * 5 + l];
            if (l == 0) { s[BSC_OBS + 90] = 0.f; s[BSC_OBS + 91] = 0.f; }
            s[BSC_HIN + l]      = hp[l];
            s[BSC_HIN + 32 + l] = hp[l + 32];
        }
        __syncwarp();

        // ---- stage 6: x = relu(obs_comb @ w_fc1 + b_fc1); X overlays OBS ----
        {
            u64 xlo2[EPW_B], xhi2[EPW_B];
            #pragma unroll
            for (int e = 0; e < EPW_B; e++) { xlo2[e] = 0; xhi2[e] = 0; }
            const float* wloP = sm + B_WFC1T + l * 92;
            const float* whiP = sm + B_WFC1T + (l + 32) * 92;
            #pragma unroll 23
            for (int cq = 0; cq < 23; cq++) {
                const ulonglong2 wl = lp4(wloP + cq * 4);
                const ulonglong2 wh = lp4(whiP + cq * 4);
                #pragma unroll
                for (int e = 0; e < EPW_B; e++) {
                    const ulonglong2 v = lp4(scr + e * B_STRIDE + BSC_OBS + cq * 4);
                    dfma2(xlo2[e], v.x, wl.x); dfma2(xlo2[e], v.y, wl.y);
                    dfma2(xhi2[e], v.x, wh.x); dfma2(xhi2[e], v.y, wh.y);
                }
            }
            __syncwarp();   // all OBS reads complete before X overwrites
            #pragma unroll
            for (int e = 0; e < EPW_B; e++) {
                scr[e * B_STRIDE + BSC_X + l]      = fmaxf(blo + f2sum(xlo2[e]), 0.f);
                scr[e * B_STRIDE + BSC_X + 32 + l] = fmaxf(bhi + f2sum(xhi2[e]), 0.f);
            }
        }
        __syncwarp();

        // ---- stage 7: GRU (two h2 passes, 4 gates per pass) + q projection ----
        {
            float hnew0[EPW_B];   // h2=0 hnew, kept for q projection

            #pragma unroll
            for (int h2 = 0; h2 < 2; h2++) {
                const int g0 = h2 * 32 + l;
                const float* wiB = sm + B_WIHT + g0 * 68;
                const float* whB = sm + B_WHHT + g0 * 68;

                u64 sr2[EPW_B], sz2[EPW_B], gn2[EPW_B], hn2[EPW_B];
                #pragma unroll
                for (int e = 0; e < EPW_B; e++) { sr2[e] = 0; sz2[e] = 0; gn2[e] = 0; hn2[e] = 0; }
                #pragma unroll 4
                for (int cq = 0; cq < 16; cq++) {
                    const ulonglong2 wir = lp4(wiB + cq * 4);
                    const ulonglong2 wiz = lp4(wiB + 64 * 68 + cq * 4);
                    const ulonglong2 win = lp4(wiB + 128 * 68 + cq * 4);
                    const ulonglong2 whr = lp4(whB + cq * 4);
                    const ulonglong2 whz = lp4(whB + 64 * 68 + cq * 4);
                    const ulonglong2 whn = lp4(whB + 128 * 68 + cq * 4);
                    #pragma unroll
                    for (int e = 0; e < EPW_B; e++) {
                        const ulonglong2 xv = lp4(scr + e * B_STRIDE + BSC_X   + cq * 4);
                        const ulonglong2 hv = lp4(scr + e * B_STRIDE + BSC_HIN + cq * 4);
                        dfma2(sr2[e], xv.x, wir.x); dfma2(sr2[e], xv.y, wir.y);
                        dfma2(sr2[e], hv.x, whr.x); dfma2(sr2[e], hv.y, whr.y);
                        dfma2(sz2[e], xv.x, wiz.x); dfma2(sz2[e], xv.y, wiz.y);
                        dfma2(sz2[e], hv.x, whz.x); dfma2(sz2[e], hv.y, whz.y);
                        dfma2(gn2[e], xv.x, win.x); dfma2(gn2[e], xv.y, win.y);
                        dfma2(hn2[e], hv.x, whn.x); dfma2(hn2[e], hv.y, whn.y);
                    }
                }
                const float br  = sm[B_BIH + g0]      + sm[B_BHH + g0];
                const float bz  = sm[B_BIH + 64 + g0] + sm[B_BHH + 64 + g0];
                const float bgn = sm[B_BIH + 128 + g0];
                const float bhn = sm[B_BHH + 128 + g0];
                #pragma unroll
                for (int e = 0; e < EPW_B; e++) {
                    const float rr = sigmoidf_(br + f2sum(sr2[e]));
                    const float zz = sigmoidf_(bz + f2sum(sz2[e]));
                    const float nn = tanhf_((bgn + f2sum(gn2[e])) + rr * (bhn + f2sum(hn2[e])));
                    const float hprev = scr[e * B_STRIDE + BSC_HIN + g0];
                    const float hnew  = (1.0f - zz) * nn + zz * hprev;
                    out[HOFF + (size_t)(e0 + e) * 64 + g0] = hnew;
                    if (h2 == 0) {
                        hnew0[e] = hnew;
                    } else {
                        // q projection + packed reduction (weights from smem, broadcast)
                        float qp0 = hnew0[e] * sm[B_WFC2 + l * 5 + 0] + hnew * sm[B_WFC2 + g0 * 5 + 0];
                        float qp1 = hnew0[e] * sm[B_WFC2 + l * 5 + 1] + hnew * sm[B_WFC2 + g0 * 5 + 1];
                        float qp2 = hnew0[e] * sm[B_WFC2 + l * 5 + 2] + hnew * sm[B_WFC2 + g0 * 5 + 2];
                        float qp3 = hnew0[e] * sm[B_WFC2 + l * 5 + 3] + hnew * sm[B_WFC2 + g0 * 5 + 3];
                        float qp4 = hnew0[e] * sm[B_WFC2 + l * 5 + 4] + hnew * sm[B_WFC2 + g0 * 5 + 4];
                        float a0 = qp0 + __shfl_xor_sync(FULLMASK, qp0, 16);
                        float a1 = qp1 + __shfl_xor_sync(FULLMASK, qp1, 16);
                        float a2 = qp2 + __shfl_xor_sync(FULLMASK, qp2, 16);
                        float a3 = qp3 + __shfl_xor_sync(FULLMASK, qp3, 16);
                        float a4 = qp4 + __shfl_xor_sync(FULLMASK, qp4, 16);
                        float z1 = (l < 16) ? a0 : a1;
                        float z2 = (l < 16) ? a2 : a3;
                        z1 += __shfl_xor_sync(FULLMASK, z1, 8);
                        z2 += __shfl_xor_sync(FULLMASK, z2, 8);
                        a4 += __shfl_xor_sync(FULLMASK, a4, 8);
                        float w = (l & 8) ? z2 : z1;
                        w  += __shfl_xor_sync(FULLMASK, w, 4);
                        w  += __shfl_xor_sync(FULLMASK, w, 2);
                        w  += __shfl_xor_sync(FULLMASK, w, 1);
                        a4 += __shfl_xor_sync(FULLMASK, a4, 4);
                        a4 += __shfl_xor_sync(FULLMASK, a4, 2);
                        a4 += __shfl_xor_sync(FULLMASK, a4, 1);
                        float* qo = out + (size_t)(e0 + e) * 5;
                        if (l == 0) {
                            qo[0] = w  + sm[B_BFC2 + 0];
                            qo[4] = a4 + sm[B_BFC2 + 4];
                        } else if (l == 8) {
                            qo[2] = w + sm[B_BFC2 + 2];
                        } else if (l == 16) {
                            qo[1] = w + sm[B_BFC2 + 1];
                        } else if (l == 24) {
                            qo[3] = w + sm[B_BFC2 + 3];
                        }
                    }
                }
            }
        }
        __syncwarp();
    }
}

extern "C" void kernel_launch(void* const* d_in, const int* in_sizes, int n_in,
                              void* d_out, int out_size) {
    (void)in_sizes; (void)n_in; (void)out_size;
    int dev = 0;
    cudaGetDevice(&dev);
    int nsm = 148;
    cudaDeviceGetAttribute(&nsm, cudaDevAttrMultiProcessorCount, dev);
    cudaFuncSetAttribute(atom_rnn_attn, cudaFuncAttributeMaxDynamicSharedMemorySize, SMEM_A);
    cudaFuncSetAttribute(atom_rnn_gru,  cudaFuncAttributeMaxDynamicSharedMemorySize, SMEM_B);

    atom_rnn_attn<<<nsm, THREADS_A, SMEM_A>>>(
        (const float*)d_in[0],
        (const float*)d_in[2],  (const float*)d_in[3],
        (const float*)d_in[4],  (const float*)d_in[5],
        (const float*)d_in[6],  (const float*)d_in[7],
        (const float*)d_in[8],  (const float*)d_in[9],
        (const float*)d_in[10], (const float*)d_in[11],
        (const float*)d_in[12], (const float*)d_in[13],
        (const float*)d_in[14], (const float*)d_in[15]);

    atom_rnn_gru<<<nsm, THREADS_B, SMEM_B>>>(
        (const float*)d_in[0],  (const float*)d_in[1],
        (const float*)d_in[16], (const float*)d_in[17],
        (const float*)d_in[18], (const float*)d_in[19],
        (const float*)d_in[20], (const float*)d_in[21],
        (const float*)d_in[22], (const float*)d_in[23],
        (float*)d_out);
}

// round 14
// speedup vs baseline: 1.1546x; 1.1413x over previous
#include <cuda_runtime.h>

#define FULLMASK 0xffffffffu

typedef unsigned long long u64;

constexpr int BATCH  = 65536;
constexpr int HOFF   = BATCH * 5;      // h output offset (q first, then h)

// ===================== kernel A (attention, stages 0-5) =====================
// 16 warps x EPW 2, 2 blocks/SM (64-reg cap) — occupancy play
constexpr int WARPS_A   = 16;
constexpr int EPW_A     = 2;
constexpr int THREADS_A = WARPS_A * 32;    // 512

constexpr int A_WINT  = 0;       // 3 * 64 rows * 12 = 2304
constexpr int A_BIN   = 2304;    // 192
constexpr int A_WA    = 2496;    // 128
constexpr int A_WO1T  = 2624;    // 384
constexpr int A_BO1   = 3008;    // 32
constexpr int A_WO2T  = 3040;    // 576
constexpr int A_BO2   = 3616;    // 16
constexpr int A_WO3   = 3632;    // 16
constexpr int A_BO3   = 3648;    // 4
constexpr int A_SCR   = 3652;

constexpr int ASC_OBS = 0;    // 88 (obs 85 + pad)
constexpr int ASC_U1  = 88;   // 160: HP1 5x32
constexpr int ASC_U2  = 248;  // 84: WH 20 | ATT 5x12 @+24 | HP2 80
constexpr int ASC_WH  = ASC_U2;
constexpr int ASC_ATT = ASC_U2 + 24;
constexpr int ASC_HP2 = ASC_U2;
constexpr int A_STRIDE = 336;

constexpr int SMEM_A = (A_SCR + WARPS_A * EPW_A * A_STRIDE) * 4;   // 57616 B -> 2 blocks/SM

// ===================== kernel B (fc1 + GRU + q, stages 6-7) =================
// R8-proven config: 16 warps x EPW 4, 1 block/SM
constexpr int WARPS_B   = 16;
constexpr int EPW_B     = 4;
constexpr int THREADS_B = WARPS_B * 32;    // 512

constexpr int B_WFC1T = 0;       // 64 rows * 92 = 5888
constexpr int B_BFC1  = 5888;    // 64
constexpr int B_WFC2  = 5952;    // 320
constexpr int B_BFC2  = 6272;    // 8
constexpr int B_WIHT  = 6280;    // 192 rows * 68 = 13056
constexpr int B_BIH   = 19336;   // 192
constexpr int B_WHHT  = 19528;   // 13056
constexpr int B_BHH   = 32584;   // 192
constexpr int B_SCR   = 32776;

constexpr int BSC_OBS = 0;    // 92 (obs 85 + obs_out 5 + pads 90,91=0)
constexpr int BSC_HIN = 92;   // 64
constexpr int BSC_X   = 156;  // 64
constexpr int B_STRIDE = 224;

constexpr int SMEM_B = (B_SCR + WARPS_B * EPW_B * B_STRIDE) * 4;   // 188448 B

__device__ float g_obs_out[BATCH * 5];

__device__ __forceinline__ float leakyf(float x)    { return fmaxf(x, 0.01f * x); }
__device__ __forceinline__ float sigmoidf_(float x) { return 1.0f / (1.0f + __expf(-x)); }
__device__ __forceinline__ float tanhf_(float x)    { float t = __expf(2.0f * x); return 1.0f - __fdividef(2.0f, t + 1.0f); }

__device__ __forceinline__ void dfma2(u64& acc, u64 v, u64 w) {
    asm("fma.rn.f32x2 %0, %1, %2, %0;" : "+l"(acc) : "l"(v), "l"(w));
}
__device__ __forceinline__ float f2sum(u64 a) {
    float lo, hi;
    asm("mov.b64 {%0, %1}, %2;" : "=f"(lo), "=f"(hi) : "l"(a));
    return lo + hi;
}
__device__ __forceinline__ ulonglong2 lp4(const float* p) {
    return *reinterpret_cast<const ulonglong2*>(p);
}

// ============================================================================
// Kernel A: stages 0-5 -> g_obs_out   (16 warps x EPW 2, 2 blocks/SM)
// ============================================================================
__global__ __launch_bounds__(THREADS_A, 2)
void atom_rnn_attn(
    const float* __restrict__ obs,
    const float* __restrict__ w_in0,  const float* __restrict__ b_in0,
    const float* __restrict__ w_in1,  const float* __restrict__ b_in1,
    const float* __restrict__ w_in2,  const float* __restrict__ b_in2,
    const float* __restrict__ W,      const float* __restrict__ a,
    const float* __restrict__ w_o1,   const float* __restrict__ b_o1,
    const float* __restrict__ w_o2,   const float* __restrict__ b_o2,
    const float* __restrict__ w_o3,   const float* __restrict__ b_o3)
{
    extern __shared__ float sm[];
    const int tid = threadIdx.x;
    const int wid = tid >> 5;
    const int l   = tid & 31;

    // ---- weight staging ----
    for (int i = tid; i < 512; i += THREADS_A) {
        int f = i >> 6, r = i & 63;
        sm[A_WINT +        r * 12 + f] = w_in0[i];
        sm[A_WINT +  768 + r * 12 + f] = w_in1[i];
        sm[A_WINT + 1536 + r * 12 + f] = w_in2[i];
    }
    for (int i = tid; i < 320; i += THREADS_A) {
        int c = i >> 5, o = i & 31;
        sm[A_WO1T + o * 12 + c] = w_o1[i];
    }
    if (tid < 64) sm[A_WO1T + (tid >> 1) * 12 + 10 + (tid & 1)] = 0.f;
    for (int i = tid; i < 512; i += THREADS_A) {
        int c = i >> 4, o = i & 15;
        sm[A_WO2T + o * 36 + c] = w_o2[i];
    }
    if (tid < 64) {
        sm[A_BIN + tid]       = b_in0[tid];
        sm[A_BIN + 64 + tid]  = b_in1[tid];
        sm[A_BIN + 128 + tid] = b_in2[tid];
        float a0 = 0.f, a1 = 0.f;                  // fold W @ a
        for (int i = 0; i < 64; i++) {
            float w = W[i * 64 + tid];
            a0 += w * a[i];
            a1 += w * a[64 + i];
        }
        sm[A_WA + tid]      = a0;
        sm[A_WA + 64 + tid] = a1;
    }
    if (tid < 32) sm[A_BO1 + tid] = b_o1[tid];
    if (tid < 16) { sm[A_BO2 + tid] = b_o2[tid]; sm[A_WO3 + tid] = w_o3[tid]; }
    if (tid == 0) sm[A_BO3] = b_o3[0];
    __syncthreads();

    float* scr = sm + A_SCR + (wid * EPW_A) * A_STRIDE;
    const int stride = gridDim.x * WARPS_A * EPW_A;

    const float wa0l = sm[A_WA + l],      wa0h = sm[A_WA + 32 + l];
    const float wa1l = sm[A_WA + 64 + l], wa1h = sm[A_WA + 96 + l];

    for (int e0 = (blockIdx.x * WARPS_A + wid) * EPW_A; e0 < BATCH; e0 += stride) {

        // ---- stage 0: load obs ----
        #pragma unroll
        for (int e = 0; e < EPW_A; e++) {
            const float* op = obs + (size_t)(e0 + e) * 85;
            float* s = scr + e * A_STRIDE;
            #pragma unroll
            for (int i = 0; i < 3; i++) {
                int idx = l + i * 32;
                if (idx < 85) s[ASC_OBS + idx] = op[idx];
            }
        }
        __syncwarp();

        // ---- stage 1: token nets (hoisted weights, packed) -> WH[0..19] ----
        {
            ulonglong2 wlA, wlB, whA, whB; float blo, bhi;
            {
                const float* wb = sm + A_WINT;   // net 0
                wlA = lp4(wb + l * 12);        wlB = lp4(wb + l * 12 + 4);
                whA = lp4(wb + (l + 32) * 12); whB = lp4(wb + (l + 32) * 12 + 4);
                blo = sm[A_BIN + l]; bhi = sm[A_BIN + 32 + l];
            }
            #pragma unroll
            for (int tp = 0; tp < 5; tp++) {
                float P1[2][EPW_A], P2[2][EPW_A];
                #pragma unroll
                for (int half = 0; half < 2; half++) {
                    const int t = 2 * tp + half;
                    if (t == 5) {
                        const float* wb = sm + A_WINT + 768;   // net 1
                        wlA = lp4(wb + l * 12);        wlB = lp4(wb + l * 12 + 4);
                        whA = lp4(wb + (l + 32) * 12); whB = lp4(wb + (l + 32) * 12 + 4);
                        blo = sm[A_BIN + 64 + l]; bhi = sm[A_BIN + 96 + l];
                    }
                    if (t == 9) {
                        const float* wb = sm + A_WINT + 1536;  // net 2
                        wlA = lp4(wb + l * 12);        wlB = lp4(wb + l * 12 + 4);
                        whA = lp4(wb + (l + 32) * 12); whB = lp4(wb + (l + 32) * 12 + 4);
                        blo = sm[A_BIN + 128 + l]; bhi = sm[A_BIN + 160 + l];
                    }
                    #pragma unroll
                    for (int e = 0; e < EPW_A; e++) {
                        const float* s = scr + e * A_STRIDE;
                        // rolled[t*8..t*8+7] == obs[t*8+4..t*8+11] (token 9 wraps)
                        ulonglong2 v0 = lp4(s + ASC_OBS + t * 8 + 4);
                        ulonglong2 v1 = (t == 9) ? lp4(s + ASC_OBS) : lp4(s + ASC_OBS + t * 8 + 8);
                        u64 accl = 0, acch = 0;
                        dfma2(accl, v0.x, wlA.x); dfma2(accl, v0.y, wlA.y);
                        dfma2(accl, v1.x, wlB.x); dfma2(accl, v1.y, wlB.y);
                        dfma2(acch, v0.x, whA.x); dfma2(acch, v0.y, whA.y);
                        dfma2(acch, v1.x, whB.x); dfma2(acch, v1.y, whB.y);
                        float hl = leakyf(blo + f2sum(accl));
                        float hh = leakyf(bhi + f2sum(acch));
                        P1[half][e] = hl * wa0l + hh * wa0h;
                        P2[half][e] = hl * wa1l + hh * wa1h;
                    }
                }
                const int t = 2 * tp;
                #pragma unroll
                for (int e = 0; e < EPW_A; e++) {
                    float* s = scr + e * A_STRIDE;
                    float aa = P1[0][e] + __shfl_xor_sync(FULLMASK, P1[0][e], 16);
                    float bb = P2[0][e] + __shfl_xor_sync(FULLMASK, P2[0][e], 16);
                    float cc = P1[1][e] + __shfl_xor_sync(FULLMASK, P1[1][e], 16);
                    float dd = P2[1][e] + __shfl_xor_sync(FULLMASK, P2[1][e], 16);
                    float za = (l < 16) ? aa : bb;
                    float zc = (l < 16) ? cc : dd;
                    za += __shfl_xor_sync(FULLMASK, za, 8);
                    zc += __shfl_xor_sync(FULLMASK, zc, 8);
                    float z = ((l & 8) == 0) ? za : zc;
                    z += __shfl_xor_sync(FULLMASK, z, 4);
                    z += __shfl_xor_sync(FULLMASK, z, 2);
                    z += __shfl_xor_sync(FULLMASK, z, 1);
                    if      (l == 0)  s[ASC_WH + t]      = z;
                    else if (l == 8)  s[ASC_WH + t + 1]  = z;
                    else if (l == 16) s[ASC_WH + 10 + t] = z;
                    else if (l == 24) s[ASC_WH + 11 + t] = z;
                }
            }
        }
        __syncwarp();

        // ---- stage 2: attention softmaxes ----
        #pragma unroll
        for (int e = 0; e < EPW_A; e++) {
            float* s = scr + e * A_STRIDE;
            if (l < 10) {
                float ev[5]; float m = -1e30f;
                const float w1 = s[ASC_WH + l];
                if (l < 5) {
                    #pragma unroll
                    for (int c = 0; c < 5; c++) {
                        float v = leakyf(w1 + s[ASC_WH + 15 + c]);
                        ev[c] = v; m = fmaxf(m, v);
                    }
                } else {
                    #pragma unroll
                    for (int c = 0; c < 5; c++) {
                        float v = leakyf(w1 + s[ASC_WH + 10 + c]);
                        ev[c] = v; m = fmaxf(m, v);
                    }
                }
                float ssum = 0.f;
                #pragma unroll
                for (int c = 0; c < 5; c++) { ev[c] = __expf(ev[c] - m); ssum += ev[c]; }
                const float inv = __fdividef(1.0f, ssum);
                if (l < 5) {
                    #pragma unroll
                    for (int c = 0; c < 5; c++) s[ASC_ATT + l * 12 + c] = ev[c] * inv;
                } else {
                    const int q = l - 5;
                    #pragma unroll
                    for (int c = 0; c < 5; c++) s[ASC_ATT + c * 12 + 5 + q] = ev[c] * inv;
                }
            } else if (l < 20) {
                const int i = l - 10;
                s[ASC_ATT + (i >> 1) * 12 + 10 + (i & 1)] = 0.f;
            }
        }
        __syncwarp();

        // ---- stage 3: hp1 ----
        {
            const ulonglong2 w1a = lp4(sm + A_WO1T + l * 12);
            const ulonglong2 w1b = lp4(sm + A_WO1T + l * 12 + 4);
            const ulonglong2 w1c = lp4(sm + A_WO1T + l * 12 + 8);
            const float bo1v = sm[A_BO1 + l];
            #pragma unroll
            for (int k = 0; k < 5; k++) {
                #pragma unroll
                for (int e = 0; e < EPW_A; e++) {
                    float* s = scr + e * A_STRIDE;
                    ulonglong2 t0 = lp4(s + ASC_ATT + k * 12);
                    ulonglong2 t1 = lp4(s + ASC_ATT + k * 12 + 4);
                    ulonglong2 t2 = lp4(s + ASC_ATT + k * 12 + 8);
                    u64 acc = 0;
                    dfma2(acc, t0.x, w1a.x); dfma2(acc, t0.y, w1a.y);
                    dfma2(acc, t1.x, w1b.x); dfma2(acc, t1.y, w1b.y);
                    dfma2(acc, t2.x, w1c.x); dfma2(acc, t2.y, w1c.y);
                    s[ASC_U1 + k * 32 + l] = leakyf(bo1v + f2sum(acc));
                }
            }
        }
        __syncwarp();

        // ---- stage 4: hp2 ----
        {
            ulonglong2 w2[8];
            #pragma unroll
            for (int q = 0; q < 8; q++) w2[q] = lp4(sm + A_WO2T + (l & 15) * 36 + q * 4);
            const float bo2v = sm[A_BO2 + (l & 15)];
            #pragma unroll
            for (int k = 0; k < 3; k++) {
                const int idx = l + 32 * k;
                const bool act = idx < 80;
                const int r = idx >> 4;
                #pragma unroll
                for (int e = 0; e < EPW_A; e++) {
                    float* s = scr + e * A_STRIDE;
                    const float* hp = s + ASC_U1 + r * 32;
                    u64 acc = 0;
                    #pragma unroll
                    for (int q = 0; q < 8; q++) {
                        ulonglong2 hv = lp4(hp + q * 4);
                        dfma2(acc, hv.x, w2[q].x);
                        dfma2(acc, hv.y, w2[q].y);
                    }
                    if (act) s[ASC_HP2 + idx] = leakyf(bo2v + f2sum(acc));
                }
            }
        }
        __syncwarp();

        // ---- stage 5: hp3 + softmax -> g_obs_out ----
        {
            ulonglong2 w3a = lp4(sm + A_WO3), w3b = lp4(sm + A_WO3 + 8);
            const float bo3v = sm[A_BO3];
            #pragma unroll
            for (int e = 0; e < EPW_A; e++) {
                float* s = scr + e * A_STRIDE;
                const int r = (l < 5) ? l : 4;
                const float* h2p = s + ASC_HP2 + r * 16;
                ulonglong2 p0 = lp4(h2p), p1 = lp4(h2p + 8);
                u64 acc = 0;
                dfma2(acc, p0.x, w3a.x); dfma2(acc, p0.y, w3a.y);
                dfma2(acc, p1.x, w3b.x); dfma2(acc, p1.y, w3b.y);
                const float v = leakyf(bo3v + f2sum(acc));
                const float v0 = __shfl_sync(FULLMASK, v, 0);
                const float v1 = __shfl_sync(FULLMASK, v, 1);
                const float v2 = __shfl_sync(FULLMASK, v, 2);
                const float v3 = __shfl_sync(FULLMASK, v, 3);
                const float v4 = __shfl_sync(FULLMASK, v, 4);
                const float m  = fmaxf(fmaxf(fmaxf(v0, v1), fmaxf(v2, v3)), v4);
                const float ssum = __expf(v0 - m) + __expf(v1 - m) + __expf(v2 - m)
                                 + __expf(v3 - m) + __expf(v4 - m);
                if (l < 5)
                    g_obs_out[(size_t)(e0 + e) * 5 + l] = __fdividef(__expf(v - m), ssum);
            }
        }
        __syncwarp();
    }
}

// ============================================================================
// Kernel B: stages 6-7 (fc1 + GRU + q) — 16 warps x EPW 4 (R8 verbatim)
// ============================================================================
__global__ __launch_bounds__(THREADS_B, 1)
void atom_rnn_gru(
    const float* __restrict__ obs,    const float* __restrict__ hidden,
    const float* __restrict__ w_fc1,  const float* __restrict__ b_fc1,
    const float* __restrict__ w_ih,   const float* __restrict__ w_hh,
    const float* __restrict__ b_ih,   const float* __restrict__ b_hh,
    const float* __restrict__ w_fc2,  const float* __restrict__ b_fc2,
    float* __restrict__ out)
{
    extern __shared__ float sm[];
    const int tid = threadIdx.x;
    const int wid = tid >> 5;
    const int l   = tid & 31;

    // ---- weight staging ----
    for (int i = tid; i < 5760; i += THREADS_B) {
        int c = i >> 6, j = i & 63;
        sm[B_WFC1T + j * 92 + c] = w_fc1[i];
    }
    for (int i = tid; i < 128; i += THREADS_B) sm[B_WFC1T + (i >> 1) * 92 + 90 + (i & 1)] = 0.f;
    for (int i = tid; i < 192 * 64; i += THREADS_B) {
        int g = i >> 6, c = i & 63;
        sm[B_WIHT + g * 68 + c] = w_ih[i];
        sm[B_WHHT + g * 68 + c] = w_hh[i];
    }
    for (int i = tid; i < 192; i += THREADS_B) { sm[B_BIH + i] = b_ih[i]; sm[B_BHH + i] = b_hh[i]; }
    for (int i = tid; i < 320; i += THREADS_B) sm[B_WFC2 + i] = w_fc2[i];
    if (tid < 64) sm[B_BFC1 + tid] = b_fc1[tid];
    if (tid < 5)  sm[B_BFC2 + tid] = b_fc2[tid];
    __syncthreads();

    float* scr = sm + B_SCR + (wid * EPW_B) * B_STRIDE;
    const int stride = gridDim.x * WARPS_B * EPW_B;

    for (int e0 = (blockIdx.x * WARPS_B + wid) * EPW_B; e0 < BATCH; e0 += stride) {

        // ---- load obs + obs_out + hidden ----
        #pragma unroll
        for (int e = 0; e < EPW_B; e++) {
            const float* op = obs    + (size_t)(e0 + e) * 85;
            const float* hp = hidden + (size_t)(e0 + e) * 64;
            float* s = scr + e * B_STRIDE;
            #pragma unroll
            for (int i = 0; i < 3; i++) {
                int idx = l + i * 32;
                if (idx < 85) s[BSC_OBS + idx] = op[idx];
            }
            if (l < 5) s[BSC_OBS + 85 + l] = g_obs_out[(size_t)(e0 + e) * 5 + l];
            if (l == 0) { s[BSC_OBS + 90] = 0.f; s[BSC_OBS + 91] = 0.f; }
            s[BSC_HIN + l]      = hp[l];
            s[BSC_HIN + 32 + l] = hp[l + 32];
        }
        __syncwarp();

        // ---- stage 6: x = relu(obs_comb @ w_fc1 + b_fc1) ----
        {
            u64 xlo2[EPW_B], xhi2[EPW_B];
            #pragma unroll
            for (int e = 0; e < EPW_B; e++) { xlo2[e] = 0; xhi2[e] = 0; }
            const float* wloP = sm + B_WFC1T + l * 92;
            const float* whiP = sm + B_WFC1T + (l + 32) * 92;
            #pragma unroll 23
            for (int cq = 0; cq < 23; cq++) {
                const ulonglong2 wl = lp4(wloP + cq * 4);
                const ulonglong2 wh = lp4(whiP + cq * 4);
                #pragma unroll
                for (int e = 0; e < EPW_B; e++) {
                    const ulonglong2 v = lp4(scr + e * B_STRIDE + BSC_OBS + cq * 4);
                    dfma2(xlo2[e], v.x, wl.x); dfma2(xlo2[e], v.y, wl.y);
                    dfma2(xhi2[e], v.x, wh.x); dfma2(xhi2[e], v.y, wh.y);
                }
            }
            const float blo = sm[B_BFC1 + l], bhi = sm[B_BFC1 + 32 + l];
            #pragma unroll
            for (int e = 0; e < EPW_B; e++) {
                scr[e * B_STRIDE + BSC_X + l]      = fmaxf(blo + f2sum(xlo2[e]), 0.f);
                scr[e * B_STRIDE + BSC_X + 32 + l] = fmaxf(bhi + f2sum(xhi2[e]), 0.f);
            }
        }
        __syncwarp();

        // ---- stage 7: GRU (two h2 passes) + q projection ----
        {
            float qp[5][EPW_B];
            #pragma unroll
            for (int k = 0; k < 5; k++)
                #pragma unroll
                for (int e = 0; e < EPW_B; e++) qp[k][e] = 0.f;

            #pragma unroll
            for (int h2 = 0; h2 < 2; h2++) {
                const int g0 = h2 * 32 + l;
                u64 sr2[EPW_B], sz2[EPW_B], gn2[EPW_B], hn2[EPW_B];
                #pragma unroll
                for (int e = 0; e < EPW_B; e++) { sr2[e] = 0; sz2[e] = 0; gn2[e] = 0; hn2[e] = 0; }
                const float* wiB = sm + B_WIHT + g0 * 68;
                const float* whB = sm + B_WHHT + g0 * 68;
                #pragma unroll 4
                for (int cq = 0; cq < 16; cq++) {
                    const ulonglong2 wir = lp4(wiB + cq * 4);
                    const ulonglong2 wiz = lp4(wiB + 64 * 68 + cq * 4);
                    const ulonglong2 win = lp4(wiB + 128 * 68 + cq * 4);
                    const ulonglong2 whr = lp4(whB + cq * 4);
                    const ulonglong2 whz = lp4(whB + 64 * 68 + cq * 4);
                    const ulonglong2 whn = lp4(whB + 128 * 68 + cq * 4);
                    #pragma unroll
                    for (int e = 0; e < EPW_B; e++) {
                        const ulonglong2 xv = lp4(scr + e * B_STRIDE + BSC_X   + cq * 4);
                        const ulonglong2 hv = lp4(scr + e * B_STRIDE + BSC_HIN + cq * 4);
                        dfma2(sr2[e], xv.x, wir.x); dfma2(sr2[e], xv.y, wir.y);
                        dfma2(sr2[e], hv.x, whr.x); dfma2(sr2[e], hv.y, whr.y);
                        dfma2(sz2[e], xv.x, wiz.x); dfma2(sz2[e], xv.y, wiz.y);
                        dfma2(sz2[e], hv.x, whz.x); dfma2(sz2[e], hv.y, whz.y);
                        dfma2(gn2[e], xv.x, win.x); dfma2(gn2[e], xv.y, win.y);
                        dfma2(hn2[e], hv.x, whn.x); dfma2(hn2[e], hv.y, whn.y);
                    }
                }
                const float br  = sm[B_BIH + g0]      + sm[B_BHH + g0];
                const float bz  = sm[B_BIH + 64 + g0] + sm[B_BHH + 64 + g0];
                const float bgn = sm[B_BIH + 128 + g0];
                const float bhn = sm[B_BHH + 128 + g0];
                #pragma unroll
                for (int e = 0; e < EPW_B; e++) {
                    const float rr = sigmoidf_(br + f2sum(sr2[e]));
                    const float zz = sigmoidf_(bz + f2sum(sz2[e]));
                    const float nn = tanhf_((bgn + f2sum(gn2[e])) + rr * (bhn + f2sum(hn2[e])));
                    const float hprev = scr[e * B_STRIDE + BSC_HIN + g0];
                    const float hnew  = (1.0f - zz) * nn + zz * hprev;
                    out[HOFF + (size_t)(e0 + e) * 64 + g0] = hnew;
                    #pragma unroll
                    for (int k = 0; k < 5; k++)
                        qp[k][e] = fmaf(hnew, sm[B_WFC2 + g0 * 5 + k], qp[k][e]);
                }
            }

            // packed q reductions
            #pragma unroll
            for (int e = 0; e < EPW_B; e++) {
                float a0 = qp[0][e] + __shfl_xor_sync(FULLMASK, qp[0][e], 16);
                float a1 = qp[1][e] + __shfl_xor_sync(FULLMASK, qp[1][e], 16);
                float a2 = qp[2][e] + __shfl_xor_sync(FULLMASK, qp[2][e], 16);
                float a3 = qp[3][e] + __shfl_xor_sync(FULLMASK, qp[3][e], 16);
                float a4 = qp[4][e] + __shfl_xor_sync(FULLMASK, qp[4][e], 16);
                float z1 = (l < 16) ? a0 : a1;
                float z2 = (l < 16) ? a2 : a3;
                z1 += __shfl_xor_sync(FULLMASK, z1, 8);
                z2 += __shfl_xor_sync(FULLMASK, z2, 8);
                a4 += __shfl_xor_sync(FULLMASK, a4, 8);
                float w = (l & 8) ? z2 : z1;
                w  += __shfl_xor_sync(FULLMASK, w, 4);
                w  += __shfl_xor_sync(FULLMASK, w, 2);
                w  += __shfl_xor_sync(FULLMASK, w, 1);
                a4 += __shfl_xor_sync(FULLMASK, a4, 4);
                a4 += __shfl_xor_sync(FULLMASK, a4, 2);
                a4 += __shfl_xor_sync(FULLMASK, a4, 1);
                float* qo = out + (size_t)(e0 + e) * 5;
                if (l == 0) {
                    qo[0] = w  + sm[B_BFC2 + 0];
                    qo[4] = a4 + sm[B_BFC2 + 4];
                } else if (l == 8) {
                    qo[2] = w + sm[B_BFC2 + 2];
                } else if (l == 16) {
                    qo[1] = w + sm[B_BFC2 + 1];
                } else if (l == 24) {
                    qo[3] = w + sm[B_BFC2 + 3];
                }
            }
        }
        __syncwarp();
    }
}

extern "C" void kernel_launch(void* const* d_in, const int* in_sizes, int n_in,
                              void* d_out, int out_size) {
    (void)in_sizes; (void)n_in; (void)out_size;
    int dev = 0;
    cudaGetDevice(&dev);
    int nsm = 148;
    cudaDeviceGetAttribute(&nsm, cudaDevAttrMultiProcessorCount, dev);
    cudaFuncSetAttribute(atom_rnn_attn, cudaFuncAttributeMaxDynamicSharedMemorySize, SMEM_A);
    cudaFuncSetAttribute(atom_rnn_gru,  cudaFuncAttributeMaxDynamicSharedMemorySize, SMEM_B);

    atom_rnn_attn<<<2 * nsm, THREADS_A, SMEM_A>>>(
        (const float*)d_in[0],
        (const float*)d_in[2],  (const float*)d_in[3],
        (const float*)d_in[4],  (const float*)d_in[5],
        (const float*)d_in[6],  (const float*)d_in[7],
        (const float*)d_in[8],  (const float*)d_in[9],
        (const float*)d_in[10], (const float*)d_in[11],
        (const float*)d_in[12], (const float*)d_in[13],
        (const float*)d_in[14], (const float*)d_in[15]);

    atom_rnn_gru<<<nsm, THREADS_B, SMEM_B>>>(
        (const float*)d_in[0],  (const float*)d_in[1],
        (const float*)d_in[16], (const float*)d_in[17],
        (const float*)d_in[18], (const float*)d_in[19],
        (const float*)d_in[20], (const float*)d_in[21],
        (const float*)d_in[22], (const float*)d_in[23],
        (float*)d_out);
}